// round 5
// baseline (speedup 1.0000x reference)
#include <cuda_runtime.h>
#include <cstdint>

#define IMG_W 4096
#define IMG_H 4096
#define PX    8   // pixels per thread

// Three-way integer min/max: official CUDA intrinsics (>=11.8, sm_90+ HW op).
// Operands are float bit patterns of values in [0, ~4.5] -> always positive,
// so signed compare == unsigned compare == float compare.
__device__ __forceinline__ int imin3(int a, int b, int c) { return __vimin3_s32(a, b, c); }
__device__ __forceinline__ int imax3(int a, int b, int c) { return __vimax3_s32(a, b, c); }

// Load 10 consecutive floats (cols x0-1 .. x0+8) of row yy, zero-padded.
__device__ __forceinline__ void load_row10(float* n, const float* __restrict__ img,
                                           int yy, int x0) {
    if ((unsigned)yy >= (unsigned)IMG_H) {
#pragma unroll
        for (int i = 0; i < 10; i++) n[i] = 0.0f;
        return;
    }
    const float* p = img + (size_t)yy * IMG_W + x0;
    float4 v0 = __ldg(reinterpret_cast<const float4*>(p));
    float4 v1 = __ldg(reinterpret_cast<const float4*>(p + 4));
    n[1] = v0.x; n[2] = v0.y; n[3] = v0.z; n[4] = v0.w;
    n[5] = v1.x; n[6] = v1.y; n[7] = v1.z; n[8] = v1.w;
    n[0] = (x0 > 0)            ? __ldg(p - 1) : 0.0f;
    n[9] = (x0 + PX < IMG_W)   ? __ldg(p + PX) : 0.0f;
}

__global__ __launch_bounds__(256)
void kirsch_mask_kernel(const float* __restrict__ img, float* __restrict__ out) {
    const int x0 = (blockIdx.x * blockDim.x + threadIdx.x) * PX;
    const int y  = blockIdx.y;

    float n0[PX + 2], n1[PX + 2], n2[PX + 2];
    load_row10(n0, img, y - 1, x0);
    load_row10(n1, img, y,     x0);
    load_row10(n2, img, y + 1, x0);

    // Shared partials: top/bottom horizontal pairs, vertical column triples.
    float pt[PX + 1], pb[PX + 1], V[PX + 2];
#pragma unroll
    for (int i = 0; i < PX + 1; i++) {
        pt[i] = n0[i] + n0[i + 1];
        pb[i] = n2[i] + n2[i + 1];
    }
#pragma unroll
    for (int i = 0; i < PX + 2; i++) V[i] = n0[i] + n1[i] + n2[i];

    float code[PX];
#pragma unroll
    for (int j = 1; j <= PX; j++) {
        // neighborhood: a=n0[j-1] b=n0[j] c=n0[j+1]
        //               d=n1[j-1]        e=n1[j+1]
        //               f=n2[j-1] g=n2[j] h=n2[j+1]
        const float c = n0[j + 1];
        const float d = n1[j - 1];
        const float e = n1[j + 1];
        const float h = n2[j + 1];

        // Kirsch response R_k = 8*P_k - 3*T (T per-pixel const) => order by P_k.
        float P[8];
        P[0] = V[j + 1];        // c+e+h  (N)
        P[1] = pt[j] + e;       // b+c+e  (NW)
        P[2] = pt[j - 1] + c;   // a+b+c  (W)
        P[3] = pt[j - 1] + d;   // a+b+d  (SW)
        P[4] = V[j - 1];        // a+d+f  (S)
        P[5] = pb[j - 1] + d;   // d+f+g  (SE)
        P[6] = pb[j - 1] + h;   // f+g+h  (E)
        P[7] = pb[j] + e;       // e+g+h  (NE)

        // All P >= 0 => integer compare of float bits == float compare.
        // Index in low 3 mantissa bits; max side uses (7-d), min side d,
        // so exact ties resolve to the FIRST index (matches argmax/argmin).
        int emin[8], emax[8];
#pragma unroll
        for (int di = 0; di < 8; di++) {
            int u = (int)(__float_as_uint(P[di]) & ~7u);  // folds into ORs (1 LOP3 each)
            emin[di] = u | di;
            emax[di] = u | (7 - di);
        }
        int wmin = imin3(emin[0], emin[1], emin[2]);
        wmin = imin3(wmin, emin[3], emin[4]);
        wmin = imin3(wmin, emin[5], emin[6]);
        wmin = min(wmin, emin[7]);

        int wmax = imax3(emax[0], emax[1], emax[2]);
        wmax = imax3(wmax, emax[3], emax[4]);
        wmax = imax3(wmax, emax[5], emax[6]);
        wmax = max(wmax, emax[7]);

        // am = 7-(wmax&7) = (wmax^7)&7 ; code = am*8 + an, converted to float
        // via exponent-bias trick (FADD on fma pipe instead of I2F).
        unsigned cb = 0x4B000000u
                    | ((((unsigned)wmax ^ 7u) << 3) & 56u)
                    | ((unsigned)wmin & 7u);
        code[j - 1] = __uint_as_float(cb) - 8388608.0f;
    }

    float4* o0 = reinterpret_cast<float4*>(out + (size_t)y * IMG_W + x0);
    o0[0] = make_float4(code[0], code[1], code[2], code[3]);
    o0[1] = make_float4(code[4], code[5], code[6], code[7]);
}

extern "C" void kernel_launch(void* const* d_in, const int* in_sizes, int n_in,
                              void* d_out, int out_size) {
    const float* img = (const float*)d_in[0];
    for (int i = 0; i < n_in; i++) {
        if (in_sizes[i] == IMG_W * IMG_H) { img = (const float*)d_in[i]; break; }
    }
    float* out = (float*)d_out;

    dim3 block(256, 1, 1);
    dim3 grid(IMG_W / (256 * PX), IMG_H, 1);  // (2, 4096)
    kirsch_mask_kernel<<<grid, block>>>(img, out);
}

// round 6
// speedup vs baseline: 1.2070x; 1.2070x over previous
#include <cuda_runtime.h>
#include <cstdint>

#define IMG_W 4096
#define IMG_H 4096
#define PX    4   // pixels per thread (PX=8 tanked occupancy: 49.7% vs 84.9%)

// Load 6 consecutive floats (cols x0-1 .. x0+4) of row yy, zero-padded.
__device__ __forceinline__ void load_row6(float* n, const float* __restrict__ img,
                                          int yy, int x0) {
    if ((unsigned)yy >= (unsigned)IMG_H) {
#pragma unroll
        for (int i = 0; i < 6; i++) n[i] = 0.0f;
        return;
    }
    const float* p = img + (size_t)yy * IMG_W + x0;
    float4 v = __ldg(reinterpret_cast<const float4*>(p));
    n[1] = v.x; n[2] = v.y; n[3] = v.z; n[4] = v.w;
    n[0] = (x0 > 0)          ? __ldg(p - 1) : 0.0f;
    n[5] = (x0 + PX < IMG_W) ? __ldg(p + PX) : 0.0f;
}

__global__ __launch_bounds__(256)
void kirsch_mask_kernel(const float* __restrict__ img, float* __restrict__ out) {
    const int x0 = (blockIdx.x * blockDim.x + threadIdx.x) * PX;
    const int y  = blockIdx.y;

    float n0[PX + 2], n1[PX + 2], n2[PX + 2];
    load_row6(n0, img, y - 1, x0);
    load_row6(n1, img, y,     x0);
    load_row6(n2, img, y + 1, x0);

    // Shared partials: top/bottom horizontal pairs, vertical column triples.
    float pt[PX + 1], pb[PX + 1], V[PX + 2];
#pragma unroll
    for (int i = 0; i < PX + 1; i++) {
        pt[i] = n0[i] + n0[i + 1];
        pb[i] = n2[i] + n2[i + 1];
    }
#pragma unroll
    for (int i = 0; i < PX + 2; i++) V[i] = n0[i] + n1[i] + n2[i];

    float code[PX];
#pragma unroll
    for (int j = 1; j <= PX; j++) {
        // neighborhood: a=n0[j-1] b=n0[j] c=n0[j+1]
        //               d=n1[j-1]        e=n1[j+1]
        //               f=n2[j-1] g=n2[j] h=n2[j+1]
        const float c = n0[j + 1];
        const float d = n1[j - 1];
        const float e = n1[j + 1];
        const float h = n2[j + 1];

        // Kirsch response R_k = 8*P_k - 3*T (T per-pixel const) => order by P_k.
        float P[8];
        P[0] = V[j + 1];        // c+e+h  (N)
        P[1] = pt[j] + e;       // b+c+e  (NW)
        P[2] = pt[j - 1] + c;   // a+b+c  (W)
        P[3] = pt[j - 1] + d;   // a+b+d  (SW)
        P[4] = V[j - 1];        // a+d+f  (S)
        P[5] = pb[j - 1] + d;   // d+f+g  (SE)
        P[6] = pb[j - 1] + h;   // f+g+h  (E)
        P[7] = pb[j] + e;       // e+g+h  (NE)

        // All P >= 0 => signed int compare of float bits == float compare.
        // tmp has low 3 bits cleared, so tmp+idx == tmp|idx (exact).
        // Max side adds (7-idx), min side adds idx => exact ties resolve to
        // the FIRST index, matching jnp.argmax/argmin.
        int tmp[8];
#pragma unroll
        for (int di = 0; di < 8; di++)
            tmp[di] = (int)(__float_as_uint(P[di]) & ~7u);   // 1 LOP3 each

        // Fused add+min/max (VIADDMNMX, sm_90+): one ALU op per direction.
        int wmin = tmp[0];                       // idx 0 is free
        wmin = __viaddmin_s32(tmp[1], 1, wmin);
        wmin = __viaddmin_s32(tmp[2], 2, wmin);
        wmin = __viaddmin_s32(tmp[3], 3, wmin);
        wmin = __viaddmin_s32(tmp[4], 4, wmin);
        wmin = __viaddmin_s32(tmp[5], 5, wmin);
        wmin = __viaddmin_s32(tmp[6], 6, wmin);
        wmin = __viaddmin_s32(tmp[7], 7, wmin);

        int wmax = tmp[0] + 7;
        wmax = __viaddmax_s32(tmp[1], 6, wmax);
        wmax = __viaddmax_s32(tmp[2], 5, wmax);
        wmax = __viaddmax_s32(tmp[3], 4, wmax);
        wmax = __viaddmax_s32(tmp[4], 3, wmax);
        wmax = __viaddmax_s32(tmp[5], 2, wmax);
        wmax = __viaddmax_s32(tmp[6], 1, wmax);
        wmax = __viaddmax_s32(tmp[7], 0, wmax);

        // am = 7-(wmax&7) = (wmax^7)&7 ; code = am*8 + an, int->float via
        // exponent-bias trick (FADD on fma pipe instead of I2F on alu pipe).
        unsigned cb = 0x4B000000u
                    | ((((unsigned)wmax ^ 7u) << 3) & 56u)
                    | ((unsigned)wmin & 7u);
        code[j - 1] = __uint_as_float(cb) - 8388608.0f;
    }

    float4* o = reinterpret_cast<float4*>(out + (size_t)y * IMG_W + x0);
    *o = make_float4(code[0], code[1], code[2], code[3]);
}

extern "C" void kernel_launch(void* const* d_in, const int* in_sizes, int n_in,
                              void* d_out, int out_size) {
    const float* img = (const float*)d_in[0];
    for (int i = 0; i < n_in; i++) {
        if (in_sizes[i] == IMG_W * IMG_H) { img = (const float*)d_in[i]; break; }
    }
    float* out = (float*)d_out;

    dim3 block(256, 1, 1);
    dim3 grid(IMG_W / (256 * PX), IMG_H, 1);  // (4, 4096)
    kirsch_mask_kernel<<<grid, block>>>(img, out);
}